// round 1
// baseline (speedup 1.0000x reference)
#include <cuda_runtime.h>
#include <cuda_bf16.h>
#include <math.h>
#include <stdint.h>

typedef __nv_bfloat16 bf16;

#define NTOK 32768          // 8*64*64 tokens
#define MDIM 4608           // 6*C modulation

// ---------------- scratch (__device__ globals; no allocation) ----------------
__device__ float g_hidden[8 * 768];
__device__ float g_m[8 * MDIM];
__device__ float g_rcos[64 * 384];
__device__ float g_rsin[64 * 384];
__device__ bf16  g_wqkv[768 * 2304];
__device__ bf16  g_wproj[768 * 768];
__device__ bf16  g_wm1[768 * 3072];
__device__ bf16  g_wm2[3072 * 768];
__device__ bf16  g_act[NTOK * 768];        // LN1 output (window order), reused for LN2 output
__device__ bf16  g_qkv[(size_t)NTOK * 2304];
__device__ bf16  g_o[NTOK * 768];          // attention output (window order)
__device__ float g_y1[NTOK * 768];         // post-attention residual (image order, fp32)
__device__ bf16  g_h[(size_t)NTOK * 3072]; // mlp hidden

// ---------------- helpers ----------------
__device__ __forceinline__ void cp16(void* s, const void* g) {
    uint32_t sa = (uint32_t)__cvta_generic_to_shared(s);
    asm volatile("cp.async.ca.shared.global [%0], [%1], 16;\n" :: "r"(sa), "l"(g));
}
__device__ __forceinline__ void cp_commit() { asm volatile("cp.async.commit_group;\n"); }
__device__ __forceinline__ void cp_wait0()  { asm volatile("cp.async.wait_group 0;\n"); }

__device__ __forceinline__ void mma16816(float* d, const uint32_t* a, const uint32_t* b) {
    asm volatile(
        "mma.sync.aligned.m16n8k16.row.col.f32.bf16.bf16.f32 "
        "{%0,%1,%2,%3},{%4,%5,%6,%7},{%8,%9},{%0,%1,%2,%3};\n"
        : "+f"(d[0]), "+f"(d[1]), "+f"(d[2]), "+f"(d[3])
        : "r"(a[0]), "r"(a[1]), "r"(a[2]), "r"(a[3]), "r"(b[0]), "r"(b[1]));
}

__device__ __forceinline__ int tok2pix(int t) {
    // window-order token -> image pixel (handles shift of 4 in both dims)
    int rem = t & 4095;
    int nh = rem >> 9, nw = (rem >> 6) & 7, l = rem & 63;
    int hh = ((nh << 3) + (l >> 3) + 60) & 63;
    int ww = ((nw << 3) + (l & 7) + 60) & 63;
    return ((t >> 12) << 12) + (hh << 6) + ww;
}

__device__ __forceinline__ float sigmoidf_(float v) { return 1.f / (1.f + expf(-v)); }

// ---------------- tiny prep kernels ----------------
__global__ void k_convert(const float* __restrict__ wq, const float* __restrict__ wp,
                          const float* __restrict__ w1, const float* __restrict__ w2) {
    const int n0 = 768 * 2304, n1 = 768 * 768, n2 = 768 * 3072, n3 = 3072 * 768;
    int total = n0 + n1 + n2 + n3;
    for (int i = blockIdx.x * blockDim.x + threadIdx.x; i < total; i += gridDim.x * blockDim.x) {
        if (i < n0)                 g_wqkv[i]            = __float2bfloat16(wq[i]);
        else if (i < n0 + n1)       g_wproj[i - n0]      = __float2bfloat16(wp[i - n0]);
        else if (i < n0 + n1 + n2)  g_wm1[i - n0 - n1]   = __float2bfloat16(w1[i - n0 - n1]);
        else                        g_wm2[i - n0 - n1 - n2] = __float2bfloat16(w2[i - n0 - n1 - n2]);
    }
}

__global__ void k_ada1(const float* __restrict__ mod, const float* __restrict__ w1,
                       const float* __restrict__ b1) {
    __shared__ float sm[768];
    int b = blockIdx.x, t = threadIdx.x;
    sm[t] = mod[b * 768 + t];
    __syncthreads();
    float acc = b1[t];
    #pragma unroll 4
    for (int k = 0; k < 768; k++) acc = fmaf(sm[k], w1[k * 768 + t], acc);
    g_hidden[b * 768 + t] = acc * sigmoidf_(acc);  // silu
}

__global__ void k_ada2(const float* __restrict__ w2, const float* __restrict__ b2) {
    __shared__ float sh[768];
    int b = blockIdx.x, t = threadIdx.x;
    sh[t] = g_hidden[b * 768 + t];
    __syncthreads();
    int col = blockIdx.y * 768 + t;
    float acc = b2[col];
    #pragma unroll 4
    for (int k = 0; k < 768; k++) acc = fmaf(sh[k], w2[k * MDIM + col], acc);
    g_m[b * MDIM + col] = acc;
}

__global__ void k_rope(const float* __restrict__ theta) {
    int l = blockIdx.x, d = threadIdx.x;
    float th = (float)(l >> 3) * theta[d] + (float)(l & 7) * theta[384 + d];
    g_rcos[l * 384 + d] = cosf(th);
    g_rsin[l * 384 + d] = sinf(th);
}

// ---------------- LayerNorm + adaLN modulate ----------------
__device__ __forceinline__ void blockReduce2(float& s, float& q) {
    #pragma unroll
    for (int o = 16; o; o >>= 1) {
        s += __shfl_xor_sync(0xffffffffu, s, o);
        q += __shfl_xor_sync(0xffffffffu, q, o);
    }
    __shared__ float rs[8], rq[8];
    int w = threadIdx.x >> 5, ln = threadIdx.x & 31;
    if (ln == 0) { rs[w] = s; rq[w] = q; }
    __syncthreads();
    if (threadIdx.x == 0) {
        float ts = 0.f, tq = 0.f;
        #pragma unroll
        for (int i = 0; i < 8; i++) { ts += rs[i]; tq += rq[i]; }
        rs[0] = ts; rq[0] = tq;
    }
    __syncthreads();
    s = rs[0]; q = rq[0];
}

// MAPPED=1: read image pixel via shift/window map, write window-order token (LN1)
// MAPPED=0: identity rows (LN2)
template <int MAPPED, int SLA, int SLB>
__global__ void __launch_bounds__(256) k_ln(const float* __restrict__ src) {
    int t = blockIdx.x;
    int b = t >> 12;
    int srow = MAPPED ? tok2pix(t) : t;
    const float* row = src + (size_t)srow * 768;
    float v[3], s = 0.f, q = 0.f;
    #pragma unroll
    for (int i = 0; i < 3; i++) {
        int c = threadIdx.x + i * 256;
        v[i] = row[c];
        s += v[i]; q += v[i] * v[i];
    }
    blockReduce2(s, q);
    float mean = s * (1.f / 768.f);
    float var = (q - 768.f * mean * mean) * (1.f / 767.f);
    float inv = rsqrtf(var + 1e-5f);
    const float* mb = g_m + b * MDIM;
    #pragma unroll
    for (int i = 0; i < 3; i++) {
        int c = threadIdx.x + i * 256;
        float a = mb[SLA * 768 + c], bb = mb[SLB * 768 + c];
        g_act[(size_t)t * 768 + c] = __float2bfloat16((v[i] - mean) * inv * (1.f + a) + bb);
    }
}

// ---------------- bf16 mma GEMM: C = A(M x K) @ B(K x N) + epilogue ----------------
// EPI 0: +bias -> g_qkv (bf16)      (A=g_act, B=g_wqkv)
// EPI 1: +bias,silu -> g_h (bf16)   (A=g_act, B=g_wm1)
// EPI 2: +bias, proj residual -> g_y1 fp32, image order (A=g_o, B=g_wproj)
// EPI 3: +bias, mlp residual  -> d_out fp32             (A=g_h, B=g_wm2)
template <int EPI, int N, int K>
__global__ void __launch_bounds__(256) k_gemm(const float* __restrict__ bias,
                                              const float* __restrict__ xres,
                                              float* __restrict__ outF) {
    const bf16* __restrict__ A  = (EPI == 0 || EPI == 1) ? g_act : (EPI == 2 ? g_o : g_h);
    const bf16* __restrict__ Bw = (EPI == 0) ? g_wqkv : (EPI == 1 ? g_wm1 : (EPI == 2 ? g_wproj : g_wm2));

    __shared__ bf16 As[2][128 * 40];
    __shared__ bf16 Bs[2][32 * 136];

    int tid = threadIdx.x, lane = tid & 31, warp = tid >> 5;
    int warpM = warp >> 2, warpN = warp & 3;          // 2 x 4 warps
    int bm = blockIdx.y * 128, bn = blockIdx.x * 128;

    float acc[4][4][4];
    #pragma unroll
    for (int i = 0; i < 4; i++)
        #pragma unroll
        for (int j = 0; j < 4; j++)
            #pragma unroll
            for (int e = 0; e < 4; e++) acc[i][j][e] = 0.f;

    int ar0 = tid >> 2, ac0 = (tid & 3) << 3;         // A: rows 0..63 / +64
    int br0 = tid >> 4, bc0 = (tid & 15) << 3;        // B: rows 0..15 / +16

    auto issue = [&](int buf, int k0) {
        cp16(&As[buf][ar0 * 40 + ac0],        A + (size_t)(bm + ar0) * K + k0 + ac0);
        cp16(&As[buf][(ar0 + 64) * 40 + ac0], A + (size_t)(bm + ar0 + 64) * K + k0 + ac0);
        cp16(&Bs[buf][br0 * 136 + bc0],        Bw + (size_t)(k0 + br0) * N + bn + bc0);
        cp16(&Bs[buf][(br0 + 16) * 136 + bc0], Bw + (size_t)(k0 + br0 + 16) * N + bn + bc0);
        cp_commit();
    };

    issue(0, 0);
    cp_wait0();
    __syncthreads();

    const int NK = K / 32;
    int buf = 0;
    int aRow = warpM * 64 + (lane & 15);
    int aColHalf = (lane >> 4) << 3;
    int bRowLane = lane & 15;
    int bColBase = warpN * 32;

    for (int kt = 0; kt < NK; kt++) {
        if (kt + 1 < NK) issue(buf ^ 1, (kt + 1) * 32);
        #pragma unroll
        for (int ks = 0; ks < 2; ks++) {
            int k0 = ks * 16;
            uint32_t a[4][4], bb[4][2];
            #pragma unroll
            for (int mt = 0; mt < 4; mt++) {
                uint32_t addr = (uint32_t)__cvta_generic_to_shared(
                    &As[buf][(aRow + mt * 16) * 40 + k0 + aColHalf]);
                asm volatile("ldmatrix.sync.aligned.m8n8.x4.shared.b16 {%0,%1,%2,%3},[%4];\n"
                             : "=r"(a[mt][0]), "=r"(a[mt][1]), "=r"(a[mt][2]), "=r"(a[mt][3])
                             : "r"(addr));
            }
            #pragma unroll
            for (int nt = 0; nt < 4; nt++) {
                uint32_t addr = (uint32_t)__cvta_generic_to_shared(
                    &Bs[buf][(k0 + bRowLane) * 136 + bColBase + nt * 8]);
                asm volatile("ldmatrix.sync.aligned.m8n8.x2.trans.shared.b16 {%0,%1},[%2];\n"
                             : "=r"(bb[nt][0]), "=r"(bb[nt][1]) : "r"(addr));
            }
            #pragma unroll
            for (int mt = 0; mt < 4; mt++)
                #pragma unroll
                for (int nt = 0; nt < 4; nt++) mma16816(acc[mt][nt], a[mt], bb[nt]);
        }
        cp_wait0();
        __syncthreads();
        buf ^= 1;
    }

    // epilogue
    int rowBase = bm + warpM * 64;
    int colBase = bn + warpN * 32;
    int r0 = lane >> 2, c0 = (lane & 3) << 1;
    #pragma unroll
    for (int mt = 0; mt < 4; mt++)
        #pragma unroll
        for (int nt = 0; nt < 4; nt++)
            #pragma unroll
            for (int half = 0; half < 2; half++) {
                int gr = rowBase + mt * 16 + r0 + half * 8;
                int gc = colBase + nt * 8 + c0;
                float v0 = acc[mt][nt][half * 2 + 0] + bias[gc];
                float v1 = acc[mt][nt][half * 2 + 1] + bias[gc + 1];
                if (EPI == 0) {
                    __nv_bfloat162 p = __floats2bfloat162_rn(v0, v1);
                    *(__nv_bfloat162*)&g_qkv[(size_t)gr * N + gc] = p;
                } else if (EPI == 1) {
                    v0 = v0 * sigmoidf_(v0);
                    v1 = v1 * sigmoidf_(v1);
                    __nv_bfloat162 p = __floats2bfloat162_rn(v0, v1);
                    *(__nv_bfloat162*)&g_h[(size_t)gr * N + gc] = p;
                } else if (EPI == 2) {
                    int pix = tok2pix(gr);
                    int b = gr >> 12;
                    float cA = g_m[b * MDIM + 2 * 768 + gc];
                    float cB = g_m[b * MDIM + 2 * 768 + gc + 1];
                    size_t o0 = (size_t)pix * 768 + gc;
                    g_y1[o0]     = (xres[o0]     + cA * v0) * rsqrtf(1.f + cA * cA);
                    g_y1[o0 + 1] = (xres[o0 + 1] + cB * v1) * rsqrtf(1.f + cB * cB);
                } else {
                    int b = gr >> 12;
                    float cA = g_m[b * MDIM + 5 * 768 + gc];
                    float cB = g_m[b * MDIM + 5 * 768 + gc + 1];
                    size_t o0 = (size_t)gr * 768 + gc;
                    outF[o0]     = (xres[o0]     + cA * v0) * rsqrtf(1.f + cA * cA);
                    outF[o0 + 1] = (xres[o0 + 1] + cB * v1) * rsqrtf(1.f + cB * cB);
                }
            }
}

// ---------------- windowed attention with RoPE (fp32 SIMT) ----------------
__global__ void __launch_bounds__(256) k_attn() {
    int win = blockIdx.x >> 4;
    int h = blockIdx.x & 15;
    __shared__ float qs[64 * 49];
    __shared__ float ks[64 * 49];
    __shared__ float S[64 * 64];
    __shared__ bf16  vs[64 * 48];

    int tid = threadIdx.x;
    const bf16* qkv = g_qkv + (size_t)win * 64 * 2304;

    for (int p = tid; p < 64 * 24; p += 256) {
        int l = p / 24, j = p % 24;
        const bf16* rp = qkv + (size_t)l * 2304 + h * 48 + 2 * j;
        float qr = __bfloat162float(rp[0]),   qi = __bfloat162float(rp[1]);
        float kr = __bfloat162float(rp[768]), ki = __bfloat162float(rp[769]);
        float co = g_rcos[l * 384 + h * 24 + j];
        float si = g_rsin[l * 384 + h * 24 + j];
        qs[l * 49 + 2 * j]     = qr * co - qi * si;
        qs[l * 49 + 2 * j + 1] = qr * si + qi * co;
        ks[l * 49 + 2 * j]     = kr * co - ki * si;
        ks[l * 49 + 2 * j + 1] = kr * si + ki * co;
    }
    for (int p = tid; p < 64 * 48; p += 256) {
        int l = p / 48, c = p % 48;
        vs[p] = qkv[(size_t)l * 2304 + 1536 + h * 48 + c];
    }
    __syncthreads();

    // S = q k^T * scale  (each thread a 4x4 tile)
    {
        int lb = (tid >> 4) * 4, mb = (tid & 15) * 4;
        float sa[4][4];
        #pragma unroll
        for (int i = 0; i < 4; i++)
            #pragma unroll
            for (int j = 0; j < 4; j++) sa[i][j] = 0.f;
        for (int c = 0; c < 48; c++) {
            float qv[4], kv[4];
            #pragma unroll
            for (int i = 0; i < 4; i++) qv[i] = qs[(lb + i) * 49 + c];
            #pragma unroll
            for (int j = 0; j < 4; j++) kv[j] = ks[(mb + j) * 49 + c];
            #pragma unroll
            for (int i = 0; i < 4; i++)
                #pragma unroll
                for (int j = 0; j < 4; j++) sa[i][j] = fmaf(qv[i], kv[j], sa[i][j]);
        }
        const float scale = 0.144337567297406441f;  // 1/sqrt(48)
        #pragma unroll
        for (int i = 0; i < 4; i++)
            #pragma unroll
            for (int j = 0; j < 4; j++) S[(lb + i) * 64 + mb + j] = sa[i][j] * scale;
    }
    __syncthreads();

    // row softmax (one warp per row)
    {
        int warp = tid >> 5, lane = tid & 31;
        for (int r = warp; r < 64; r += 8) {
            float v0 = S[r * 64 + lane], v1 = S[r * 64 + lane + 32];
            float mx = fmaxf(v0, v1);
            #pragma unroll
            for (int o = 16; o; o >>= 1) mx = fmaxf(mx, __shfl_xor_sync(0xffffffffu, mx, o));
            float e0 = expf(v0 - mx), e1 = expf(v1 - mx);
            float sm = e0 + e1;
            #pragma unroll
            for (int o = 16; o; o >>= 1) sm += __shfl_xor_sync(0xffffffffu, sm, o);
            float inv = 1.f / sm;
            S[r * 64 + lane] = e0 * inv;
            S[r * 64 + lane + 32] = e1 * inv;
        }
    }
    __syncthreads();

    // O = S @ V  (each thread a 4x3 tile)
    {
        int lb = (tid >> 4) * 4, cb = (tid & 15) * 3;
        float oa[4][3];
        #pragma unroll
        for (int i = 0; i < 4; i++)
            #pragma unroll
            for (int j = 0; j < 3; j++) oa[i][j] = 0.f;
        for (int mm = 0; mm < 64; mm++) {
            float sv[4], vv[3];
            #pragma unroll
            for (int i = 0; i < 4; i++) sv[i] = S[(lb + i) * 64 + mm];
            #pragma unroll
            for (int j = 0; j < 3; j++) vv[j] = __bfloat162float(vs[mm * 48 + cb + j]);
            #pragma unroll
            for (int i = 0; i < 4; i++)
                #pragma unroll
                for (int j = 0; j < 3; j++) oa[i][j] = fmaf(sv[i], vv[j], oa[i][j]);
        }
        #pragma unroll
        for (int i = 0; i < 4; i++)
            #pragma unroll
            for (int j = 0; j < 3; j++)
                g_o[(size_t)(win * 64 + lb + i) * 768 + h * 48 + cb + j] =
                    __float2bfloat16(oa[i][j]);
    }
}

// ---------------- launch ----------------
extern "C" void kernel_launch(void* const* d_in, const int* in_sizes, int n_in,
                              void* d_out, int out_size) {
    const float* x      = (const float*)d_in[0];
    const float* mod    = (const float*)d_in[1];
    const float* ada_w1 = (const float*)d_in[2];
    const float* ada_b1 = (const float*)d_in[3];
    const float* ada_w2 = (const float*)d_in[4];
    const float* ada_b2 = (const float*)d_in[5];
    const float* theta  = (const float*)d_in[6];
    const float* qkv_w  = (const float*)d_in[7];
    const float* qkv_b  = (const float*)d_in[8];
    const float* proj_w = (const float*)d_in[9];
    const float* proj_b = (const float*)d_in[10];
    const float* mlp_w1 = (const float*)d_in[11];
    const float* mlp_b1 = (const float*)d_in[12];
    const float* mlp_w2 = (const float*)d_in[13];
    const float* mlp_b2 = (const float*)d_in[14];
    float* out = (float*)d_out;

    k_convert<<<4096, 256>>>(qkv_w, proj_w, mlp_w1, mlp_w2);
    k_ada1<<<8, 768>>>(mod, ada_w1, ada_b1);
    k_ada2<<<dim3(8, 6), 768>>>(ada_w2, ada_b2);
    k_rope<<<64, 384>>>(theta);

    // LN1 + modulate + shift + window partition (window-order rows)
    k_ln<1, 0, 1><<<NTOK, 256>>>(x);

    // qkv GEMM: 32768x768 @ 768x2304
    k_gemm<0, 2304, 768><<<dim3(18, 256), 256>>>(qkv_b, nullptr, nullptr);

    // attention per (window, head)
    k_attn<<<512 * 16, 256>>>();

    // proj GEMM + un-window/un-shift + first residual -> g_y1 (image order)
    k_gemm<2, 768, 768><<<dim3(6, 256), 256>>>(proj_b, x, nullptr);

    // LN2 + modulate (image order)
    k_ln<0, 3, 4><<<NTOK, 256>>>(g_y1);

    // mlp1 + silu
    k_gemm<1, 3072, 768><<<dim3(24, 256), 256>>>(mlp_b1, nullptr, nullptr);

    // mlp2 + second residual -> d_out
    k_gemm<3, 768, 3072><<<dim3(6, 256), 256>>>(mlp_b2, x, out);
}